// round 5
// baseline (speedup 1.0000x reference)
#include <cuda_runtime.h>
#include <cstdint>
#include <cstddef>

// Problem constants
#define BB   32
#define TT   2048
#define HH   256
#define OBS  64
#define EMB  128
#define G4   1024   // 4*H

// ---------------- device scratch (no allocations allowed) ----------------
__device__ float g_xz[(size_t)BB * TT * G4];   // 256 MB: x-path preactivations
__device__ float g_Wc[OBS * G4];               // W_embed @ kernel
__device__ float g_bc[G4];                     // b_embed @ kernel + bias

// ---------------- kernel 1: fold the two dense layers --------------------
__global__ void prep_kernel(const float* __restrict__ W_embed,
                            const float* __restrict__ b_embed,
                            const float* __restrict__ kern,
                            const float* __restrict__ bias) {
    int j = threadIdx.x;       // 0..1023
    int i = blockIdx.x;        // 0..64 (64 = bc row)
    if (i < OBS) {
        float acc = 0.f;
        #pragma unroll 4
        for (int e = 0; e < EMB; e++)
            acc += W_embed[i * EMB + e] * kern[e * G4 + j];
        g_Wc[i * G4 + j] = acc;
    } else {
        float acc = bias[j];
        #pragma unroll 4
        for (int e = 0; e < EMB; e++)
            acc += b_embed[e] * kern[e * G4 + j];
        g_bc[j] = acc;
    }
}

// ---------------- kernel 2: xz = obs @ Wc + bc ----------------------------
#define K2_ROWS 32
__global__ void __launch_bounds__(256) xz_kernel(const float* __restrict__ obs) {
    __shared__ float obs_s[OBS * K2_ROWS];  // [k][r]
    int bid    = blockIdx.x;
    int colBlk = bid & 1;
    int rowBlk = bid >> 1;
    int row0   = rowBlk * K2_ROWS;
    int col0   = colBlk * 512;
    int tid    = threadIdx.x;

    for (int idx = tid; idx < OBS * K2_ROWS; idx += 256) {
        int r = idx >> 6, k = idx & 63;
        obs_s[k * K2_ROWS + r] = obs[(size_t)(row0 + r) * OBS + k];
    }
    __syncthreads();

    int c0 = col0 + tid;
    int c1 = c0 + 256;
    float acc0[K2_ROWS], acc1[K2_ROWS];
    #pragma unroll
    for (int r = 0; r < K2_ROWS; r++) { acc0[r] = 0.f; acc1[r] = 0.f; }

    #pragma unroll 2
    for (int k = 0; k < OBS; k++) {
        float w0 = g_Wc[k * G4 + c0];
        float w1 = g_Wc[k * G4 + c1];
        #pragma unroll
        for (int r = 0; r < K2_ROWS; r += 4) {
            float4 o4 = *(const float4*)&obs_s[k * K2_ROWS + r];
            acc0[r + 0] += o4.x * w0; acc0[r + 1] += o4.y * w0;
            acc0[r + 2] += o4.z * w0; acc0[r + 3] += o4.w * w0;
            acc1[r + 0] += o4.x * w1; acc1[r + 1] += o4.y * w1;
            acc1[r + 2] += o4.z * w1; acc1[r + 3] += o4.w * w1;
        }
    }
    float b0 = g_bc[c0], b1 = g_bc[c1];
    #pragma unroll
    for (int r = 0; r < K2_ROWS; r++) {
        size_t row = (size_t)(row0 + r);
        g_xz[row * G4 + c0] = acc0[r] + b0;
        g_xz[row * G4 + c1] = acc1[r] + b1;
    }
}

// ---------------- kernel 3: masked LSTM recurrence ------------------------
// 16 clusters x 8 CTAs; cluster owns batches {2c, 2c+1}; CTA rank owns 32
// hidden units (128 gate cols). 512 threads = (col 0..127, kq 0..3); each
// thread holds its 64-k R slice as 32 packed f32x2 regs. Per-step h
// exchange: per-warp 128-B DSMEM BULK copies (cp.async.bulk shared::cluster)
// with complete_tx onto parity mbarriers -> 16 fabric transactions per CTA
// per step instead of 512 scalar st.async.
#define CLU 8
#define TX_BYTES (64 * CLU * 4)   // 2048 B received per CTA per step

__device__ __forceinline__ void ffma2(unsigned long long& d,
                                      unsigned long long a,
                                      unsigned long long b) {
    asm("fma.rn.f32x2 %0, %1, %2, %0;" : "+l"(d) : "l"(a), "l"(b));
}
__device__ __forceinline__ unsigned long long packf2(float lo, float hi) {
    unsigned long long r;
    asm("mov.b64 %0, {%1,%2};" : "=l"(r) : "f"(lo), "f"(hi));
    return r;
}
__device__ __forceinline__ float pairsum(unsigned long long a) {
    float lo, hi;
    asm("mov.b64 {%0,%1}, %2;" : "=f"(lo), "=f"(hi) : "l"(a));
    return lo + hi;
}
// 128-B bulk copy: local smem -> peer smem, tx-signal on peer's mbarrier
__device__ __forceinline__ void blkcp128(uint32_t dst_l, uint32_t mbar_l,
                                         uint32_t peer, uint32_t src_l) {
    asm volatile(
        "{\n\t.reg .b32 rd, rb;\n\t"
        "mapa.shared::cluster.u32 rd, %0, %2;\n\t"
        "mapa.shared::cluster.u32 rb, %1, %2;\n\t"
        "cp.async.bulk.shared::cluster.shared::cta.mbarrier::complete_tx::bytes"
        " [rd], [%3], 128, [rb];\n\t}"
        :: "r"(dst_l), "r"(mbar_l), "r"(peer), "r"(src_l) : "memory");
}
__device__ __forceinline__ void mbar_init(uint32_t mbar, uint32_t cnt) {
    asm volatile("mbarrier.init.shared.b64 [%0], %1;" :: "r"(mbar), "r"(cnt) : "memory");
}
__device__ __forceinline__ void mbar_arm(uint32_t mbar, uint32_t tx) {
    asm volatile("mbarrier.arrive.expect_tx.shared.b64 _, [%0], %1;"
                 :: "r"(mbar), "r"(tx) : "memory");
}
__device__ __forceinline__ void mbar_wait(uint32_t mbar, uint32_t parity) {
    uint32_t done;
    asm volatile(
        "{\n\t.reg .pred p;\n\t"
        "mbarrier.try_wait.parity.acquire.cluster.shared::cta.b64 p, [%1], %2;\n\t"
        "selp.b32 %0, 1, 0, p;\n\t}"
        : "=r"(done) : "r"(mbar), "r"(parity) : "memory");
    if (!done) {
        asm volatile(
            "{\n\t.reg .pred P1;\n\t"
            "W_%=:\n\t"
            "mbarrier.try_wait.parity.acquire.cluster.shared::cta.b64 P1, [%0], %1, 0x989680;\n\t"
            "@P1 bra.uni D_%=;\n\t"
            "bra.uni W_%=;\n\t"
            "D_%=:\n\t}"
            :: "r"(mbar), "r"(parity) : "memory");
    }
}
__device__ __forceinline__ void cl_sync() {
    asm volatile("barrier.cluster.arrive.aligned;" ::: "memory");
    asm volatile("barrier.cluster.wait.aligned;" ::: "memory");
}

__global__ void __launch_bounds__(512, 1) __cluster_dims__(CLU, 1, 1)
rec_kernel(const float* __restrict__ S, const float* __restrict__ M,
           const float* __restrict__ rec, float* __restrict__ out) {
    __shared__ __align__(16) float hbuf[2][2][HH];     // [parity][batch][k]
    __shared__ __align__(16) float hstage[2][2][32];   // [parity][batch][unit]
    __shared__ float zpart[2][2][4][128];              // [parity][batch][kq][col]
    __shared__ __align__(8) unsigned long long mbar[2];

    const int tid  = threadIdx.x;
    const int rank = blockIdx.x & (CLU - 1);
    const int cid  = blockIdx.x / CLU;
    const int b0g  = cid * 2;

    const int col  = tid & 127;
    const int kq   = tid >> 7;            // 0..3
    const int gate = col >> 5;
    const int ul   = col & 31;
    const int j    = gate * HH + rank * 32 + ul;   // global gate column
    const int k0   = kq * 64;

    const uint32_t hbase  = (uint32_t)__cvta_generic_to_shared(&hbuf[0][0][0]);
    const uint32_t stbase = (uint32_t)__cvta_generic_to_shared(&hstage[0][0][0]);
    const uint32_t mbase  = (uint32_t)__cvta_generic_to_shared(&mbar[0]);

    // R slice -> registers as adjacent-k f32x2 pairs (32 u64 regs)
    unsigned long long R2[32];
    #pragma unroll
    for (int i = 0; i < 32; i++) {
        float r0 = rec[(unsigned)(k0 + 2 * i)     * G4 + j];
        float r1 = rec[(unsigned)(k0 + 2 * i + 1) * G4 + j];
        R2[i] = packf2(r0, r1);
    }

    // mbarriers: count=1 (the arming arrive); arm both for first uses
    if (tid == 0) {
        mbar_init(mbase, 1);
        mbar_init(mbase + 8, 1);
        asm volatile("fence.mbarrier_init.release.cluster;" ::: "memory");
        mbar_arm(mbase, TX_BYTES);
        mbar_arm(mbase + 8, TX_BYTES);
    }

    // Init h (parity 0) and c from S = [h | c]
    for (int idx = tid; idx < 2 * HH; idx += 512) {
        int b = idx >> 8, k = idx & 255;
        hbuf[0][b][k] = S[(unsigned)(b0g + b) * (2 * HH) + k];
    }
    const int gb = tid >> 5, gu = tid & 31;   // epilogue coords (tid<64)
    float c_st = 0.f;
    if (tid < 64)
        c_st = S[(unsigned)(b0g + gb) * (2 * HH) + HH + rank * 32 + gu];
    __syncthreads();
    cl_sync();   // all peers' mbarriers initialized+armed, hbuf[0] ready

    // Prefetch x-path + mask for t=0
    float xi = 0.f, xf = 0.f, xg = 0.f, xo = 0.f, mv = 0.f;
    unsigned rowoff = 0;
    if (tid < 64) {
        rowoff = (unsigned)(b0g + gb) * TT;
        const float* xr = g_xz + (size_t)rowoff * G4 + rank * 32 + gu;
        xi = xr[0]; xf = xr[HH]; xg = xr[2 * HH]; xo = xr[3 * HH];
        mv = M[rowoff];
    }

    int ph0 = 0, ph1 = 0;

    for (int t = 0; t < TT; t++) {
        const int p = t & 1;

        if (t > 0) {
            // wait for this step's h (bulk-delivered from all peers)
            if (p) { mbar_wait(mbase + 8, ph1); }
            else   { mbar_wait(mbase,     ph0); }
            if (tid == 0) mbar_arm(mbase + (p ? 8u : 0u), TX_BYTES);
            if (p) ph1 ^= 1; else ph0 ^= 1;
        }

        const ulonglong2* H0 = (const ulonglong2*)&hbuf[p][0][k0];
        const ulonglong2* H1 = (const ulonglong2*)&hbuf[p][1][k0];
        unsigned long long acc00 = 0, acc01 = 0, acc10 = 0, acc11 = 0;
        #pragma unroll
        for (int i = 0; i < 16; i++) {
            ulonglong2 h0 = H0[i];
            ulonglong2 h1 = H1[i];
            ffma2(acc00, R2[2 * i],     h0.x);
            ffma2(acc01, R2[2 * i + 1], h0.y);
            ffma2(acc10, R2[2 * i],     h1.x);
            ffma2(acc11, R2[2 * i + 1], h1.y);
        }
        zpart[p][0][kq][col] = pairsum(acc00) + pairsum(acc01);
        zpart[p][1][kq][col] = pairsum(acc10) + pairsum(acc11);
        __syncthreads();

        if (tid < 64) {
            const float keep = 1.f - mv;
            float zr_i = zpart[p][gb][0][gu]      + zpart[p][gb][1][gu]
                       + zpart[p][gb][2][gu]      + zpart[p][gb][3][gu];
            float zr_f = zpart[p][gb][0][32 + gu] + zpart[p][gb][1][32 + gu]
                       + zpart[p][gb][2][32 + gu] + zpart[p][gb][3][32 + gu];
            float zr_g = zpart[p][gb][0][64 + gu] + zpart[p][gb][1][64 + gu]
                       + zpart[p][gb][2][64 + gu] + zpart[p][gb][3][64 + gu];
            float zr_o = zpart[p][gb][0][96 + gu] + zpart[p][gb][1][96 + gu]
                       + zpart[p][gb][2][96 + gu] + zpart[p][gb][3][96 + gu];
            float zi = xi + keep * zr_i;
            float zf = xf + keep * zr_f;
            float zg = xg + keep * zr_g;
            float zo = xo + keep * zr_o;

            float ig = 1.f / (1.f + __expf(-zi));
            float fg = 1.f / (1.f + __expf(-zf));
            float gg = 1.f - 2.f / (__expf(2.f * zg) + 1.f);
            float og = 1.f / (1.f + __expf(-zo));

            float c = fg * (keep * c_st) + ig * gg;
            c_st = c;
            float th = 1.f - 2.f / (__expf(2.f * c) + 1.f);
            float hh = og * th;

            if (t < TT - 1) {
                const int pn = p ^ 1;
                // stage this warp's 32 h values, then lane 0 bulk-copies the
                // 128-B slice to hbuf[pn][gb][rank*32] in every cluster CTA
                hstage[pn][gb][gu] = hh;
                __syncwarp();
                if (gu == 0) {
                    asm volatile("fence.proxy.async.shared::cta;" ::: "memory");
                    uint32_t src  = stbase + (uint32_t)((pn * 2 + gb) * 32 * 4);
                    uint32_t dst  = hbase +
                        (uint32_t)(((pn * 2 + gb) * HH + rank * 32) * 4);
                    uint32_t lmb  = mbase + (uint32_t)(pn * 8);
                    #pragma unroll
                    for (uint32_t peer = 0; peer < CLU; peer++)
                        blkcp128(dst, lmb, peer, src);
                }

                out[(size_t)(rowoff + (unsigned)t) * HH + rank * 32 + gu] = hh;

                // prefetch next step's x/M (latency hides under peers' work)
                const float* xr = g_xz + (size_t)(rowoff + (unsigned)t + 1u) * G4
                                  + rank * 32 + gu;
                xi = xr[0]; xf = xr[HH]; xg = xr[2 * HH]; xo = xr[3 * HH];
                mv = M[rowoff + (unsigned)t + 1u];
            } else {
                out[(size_t)(rowoff + (unsigned)t) * HH + rank * 32 + gu] = hh;
            }
        }
    }
    cl_sync();   // don't exit while peers may still write our smem
}

// ---------------- launch ---------------------------------------------------
extern "C" void kernel_launch(void* const* d_in, const int* in_sizes, int n_in,
                              void* d_out, int out_size) {
    const float* obs     = (const float*)d_in[0];
    const float* S       = (const float*)d_in[1];
    const float* M       = (const float*)d_in[2];
    const float* W_embed = (const float*)d_in[3];
    const float* b_embed = (const float*)d_in[4];
    const float* kern    = (const float*)d_in[5];
    const float* rec     = (const float*)d_in[6];
    const float* bias    = (const float*)d_in[7];
    float* out = (float*)d_out;

    prep_kernel<<<65, 1024>>>(W_embed, b_embed, kern, bias);
    xz_kernel<<<4096, 256>>>(obs);
    rec_kernel<<<128, 512>>>(S, M, rec, out);
}

// round 6
// speedup vs baseline: 1.2019x; 1.2019x over previous
#include <cuda_runtime.h>
#include <cstdint>
#include <cstddef>

// Problem constants
#define BB   32
#define TT   2048
#define HH   256
#define OBS  64
#define EMB  128
#define G4   1024   // 4*H

// ---------------- device scratch (no allocations allowed) ----------------
__device__ float g_xz[(size_t)BB * TT * G4];   // 256 MB: x-path preactivations
__device__ float g_Wc[OBS * G4];               // W_embed @ kernel
__device__ float g_bc[G4];                     // b_embed @ kernel + bias

// ---------------- kernel 1: fold the two dense layers --------------------
__global__ void prep_kernel(const float* __restrict__ W_embed,
                            const float* __restrict__ b_embed,
                            const float* __restrict__ kern,
                            const float* __restrict__ bias) {
    int j = threadIdx.x;       // 0..1023
    int i = blockIdx.x;        // 0..64 (64 = bc row)
    if (i < OBS) {
        float acc = 0.f;
        #pragma unroll 4
        for (int e = 0; e < EMB; e++)
            acc += W_embed[i * EMB + e] * kern[e * G4 + j];
        g_Wc[i * G4 + j] = acc;
    } else {
        float acc = bias[j];
        #pragma unroll 4
        for (int e = 0; e < EMB; e++)
            acc += b_embed[e] * kern[e * G4 + j];
        g_bc[j] = acc;
    }
}

// ---------------- kernel 2: xz = obs @ Wc + bc ----------------------------
#define K2_ROWS 32
__global__ void __launch_bounds__(256) xz_kernel(const float* __restrict__ obs) {
    __shared__ float obs_s[OBS * K2_ROWS];  // [k][r]
    int bid    = blockIdx.x;
    int colBlk = bid & 1;
    int rowBlk = bid >> 1;
    int row0   = rowBlk * K2_ROWS;
    int col0   = colBlk * 512;
    int tid    = threadIdx.x;

    for (int idx = tid; idx < OBS * K2_ROWS; idx += 256) {
        int r = idx >> 6, k = idx & 63;
        obs_s[k * K2_ROWS + r] = obs[(size_t)(row0 + r) * OBS + k];
    }
    __syncthreads();

    int c0 = col0 + tid;
    int c1 = c0 + 256;
    float acc0[K2_ROWS], acc1[K2_ROWS];
    #pragma unroll
    for (int r = 0; r < K2_ROWS; r++) { acc0[r] = 0.f; acc1[r] = 0.f; }

    #pragma unroll 2
    for (int k = 0; k < OBS; k++) {
        float w0 = g_Wc[k * G4 + c0];
        float w1 = g_Wc[k * G4 + c1];
        #pragma unroll
        for (int r = 0; r < K2_ROWS; r += 4) {
            float4 o4 = *(const float4*)&obs_s[k * K2_ROWS + r];
            acc0[r + 0] += o4.x * w0; acc0[r + 1] += o4.y * w0;
            acc0[r + 2] += o4.z * w0; acc0[r + 3] += o4.w * w0;
            acc1[r + 0] += o4.x * w1; acc1[r + 1] += o4.y * w1;
            acc1[r + 2] += o4.z * w1; acc1[r + 3] += o4.w * w1;
        }
    }
    float b0 = g_bc[c0], b1 = g_bc[c1];
    #pragma unroll
    for (int r = 0; r < K2_ROWS; r++) {
        size_t row = (size_t)(row0 + r);
        g_xz[row * G4 + c0] = acc0[r] + b0;
        g_xz[row * G4 + c1] = acc1[r] + b1;
    }
}

// ---------------- kernel 3: masked LSTM recurrence ------------------------
// 16 clusters x 8 CTAs; cluster owns batches {2c, 2c+1}; CTA rank owns 32
// hidden units (128 gate cols). 512 threads = (col 0..127, kq 0..3); each
// thread holds its 64-k R slice as 32 packed f32x2 regs. Per-step h
// exchange: 16-B st.async.v4 from all 32 lanes of each batch-warp
// (2 stores/lane) -> 128 stores & 128 mbar tx events per CTA per step
// (vs 512 scalar in R4). No bulk engine, no proxy fence, no cluster barrier.
#define CLU 8
#define TX_BYTES (64 * CLU * 4)   // 2048 B received per CTA per step

__device__ __forceinline__ void ffma2(unsigned long long& d,
                                      unsigned long long a,
                                      unsigned long long b) {
    asm("fma.rn.f32x2 %0, %1, %2, %0;" : "+l"(d) : "l"(a), "l"(b));
}
__device__ __forceinline__ unsigned long long packf2(float lo, float hi) {
    unsigned long long r;
    asm("mov.b64 %0, {%1,%2};" : "=l"(r) : "f"(lo), "f"(hi));
    return r;
}
__device__ __forceinline__ float pairsum(unsigned long long a) {
    float lo, hi;
    asm("mov.b64 {%0,%1}, %2;" : "=f"(lo), "=f"(hi) : "l"(a));
    return lo + hi;
}
// 16-B remote store with tx-signal on the peer's mbarrier
__device__ __forceinline__ void stasync_v4(uint32_t laddr, uint32_t lmbar,
                                           uint32_t peer, uint4 v) {
    asm volatile(
        "{\n\t.reg .b32 ra, rb;\n\t"
        "mapa.shared::cluster.u32 ra, %0, %1;\n\t"
        "mapa.shared::cluster.u32 rb, %2, %1;\n\t"
        "st.async.shared::cluster.mbarrier::complete_tx::bytes.v4.b32"
        " [ra], {%3,%4,%5,%6}, [rb];\n\t}"
        :: "r"(laddr), "r"(peer), "r"(lmbar),
           "r"(v.x), "r"(v.y), "r"(v.z), "r"(v.w) : "memory");
}
__device__ __forceinline__ void mbar_init(uint32_t mbar, uint32_t cnt) {
    asm volatile("mbarrier.init.shared.b64 [%0], %1;" :: "r"(mbar), "r"(cnt) : "memory");
}
__device__ __forceinline__ void mbar_arm(uint32_t mbar, uint32_t tx) {
    asm volatile("mbarrier.arrive.expect_tx.shared.b64 _, [%0], %1;"
                 :: "r"(mbar), "r"(tx) : "memory");
}
__device__ __forceinline__ void mbar_wait(uint32_t mbar, uint32_t parity) {
    uint32_t done;
    asm volatile(
        "{\n\t.reg .pred p;\n\t"
        "mbarrier.try_wait.parity.acquire.cluster.shared::cta.b64 p, [%1], %2;\n\t"
        "selp.b32 %0, 1, 0, p;\n\t}"
        : "=r"(done) : "r"(mbar), "r"(parity) : "memory");
    if (!done) {
        asm volatile(
            "{\n\t.reg .pred P1;\n\t"
            "W_%=:\n\t"
            "mbarrier.try_wait.parity.acquire.cluster.shared::cta.b64 P1, [%0], %1, 0x989680;\n\t"
            "@P1 bra.uni D_%=;\n\t"
            "bra.uni W_%=;\n\t"
            "D_%=:\n\t}"
            :: "r"(mbar), "r"(parity) : "memory");
    }
}
__device__ __forceinline__ void cl_sync() {
    asm volatile("barrier.cluster.arrive.aligned;" ::: "memory");
    asm volatile("barrier.cluster.wait.aligned;" ::: "memory");
}

__global__ void __launch_bounds__(512, 1) __cluster_dims__(CLU, 1, 1)
rec_kernel(const float* __restrict__ S, const float* __restrict__ M,
           const float* __restrict__ rec, float* __restrict__ out) {
    __shared__ __align__(16) float hbuf[2][2][HH];     // [parity][batch][k]
    __shared__ __align__(16) float hstage[2][32];      // [batch][unit]
    __shared__ float zpart[2][2][4][128];              // [parity][batch][kq][col]
    __shared__ __align__(8) unsigned long long mbar[2];

    const int tid  = threadIdx.x;
    const int rank = blockIdx.x & (CLU - 1);
    const int cid  = blockIdx.x / CLU;
    const int b0g  = cid * 2;

    const int col  = tid & 127;
    const int kq   = tid >> 7;            // 0..3
    const int gate = col >> 5;
    const int ul   = col & 31;
    const int j    = gate * HH + rank * 32 + ul;   // global gate column
    const int k0   = kq * 64;

    const uint32_t hbase = (uint32_t)__cvta_generic_to_shared(&hbuf[0][0][0]);
    const uint32_t mbase = (uint32_t)__cvta_generic_to_shared(&mbar[0]);

    // R slice -> registers as adjacent-k f32x2 pairs (32 u64 regs)
    unsigned long long R2[32];
    #pragma unroll
    for (int i = 0; i < 32; i++) {
        float r0 = rec[(unsigned)(k0 + 2 * i)     * G4 + j];
        float r1 = rec[(unsigned)(k0 + 2 * i + 1) * G4 + j];
        R2[i] = packf2(r0, r1);
    }

    // mbarriers: count=1 (the arming arrive); arm both for first uses
    if (tid == 0) {
        mbar_init(mbase, 1);
        mbar_init(mbase + 8, 1);
        asm volatile("fence.mbarrier_init.release.cluster;" ::: "memory");
        mbar_arm(mbase, TX_BYTES);
        mbar_arm(mbase + 8, TX_BYTES);
    }

    // Init h (parity 0) and c from S = [h | c]
    for (int idx = tid; idx < 2 * HH; idx += 512) {
        int b = idx >> 8, k = idx & 255;
        hbuf[0][b][k] = S[(unsigned)(b0g + b) * (2 * HH) + k];
    }
    const int gb = tid >> 5, gu = tid & 31;   // epilogue coords (tid<64)
    float c_st = 0.f;
    if (tid < 64)
        c_st = S[(unsigned)(b0g + gb) * (2 * HH) + HH + rank * 32 + gu];
    __syncthreads();
    cl_sync();   // all peers' mbarriers initialized+armed, hbuf[0] ready

    // Prefetch x-path + mask for t=0
    float xi = 0.f, xf = 0.f, xg = 0.f, xo = 0.f, mv = 0.f;
    unsigned rowoff = 0;
    if (tid < 64) {
        rowoff = (unsigned)(b0g + gb) * TT;
        const float* xr = g_xz + (size_t)rowoff * G4 + rank * 32 + gu;
        xi = xr[0]; xf = xr[HH]; xg = xr[2 * HH]; xo = xr[3 * HH];
        mv = M[rowoff];
    }

    int ph0 = 0, ph1 = 0;

    for (int t = 0; t < TT; t++) {
        const int p = t & 1;

        if (t > 0) {
            // wait for this step's h (delivered via st.async from all peers)
            if (p) { mbar_wait(mbase + 8, ph1); }
            else   { mbar_wait(mbase,     ph0); }
            if (tid == 0) mbar_arm(mbase + (p ? 8u : 0u), TX_BYTES);
            if (p) ph1 ^= 1; else ph0 ^= 1;
        }

        const ulonglong2* H0 = (const ulonglong2*)&hbuf[p][0][k0];
        const ulonglong2* H1 = (const ulonglong2*)&hbuf[p][1][k0];
        unsigned long long acc00 = 0, acc01 = 0, acc10 = 0, acc11 = 0;
        #pragma unroll
        for (int i = 0; i < 16; i++) {
            ulonglong2 h0 = H0[i];
            ulonglong2 h1 = H1[i];
            ffma2(acc00, R2[2 * i],     h0.x);
            ffma2(acc01, R2[2 * i + 1], h0.y);
            ffma2(acc10, R2[2 * i],     h1.x);
            ffma2(acc11, R2[2 * i + 1], h1.y);
        }
        zpart[p][0][kq][col] = pairsum(acc00) + pairsum(acc01);
        zpart[p][1][kq][col] = pairsum(acc10) + pairsum(acc11);
        __syncthreads();

        if (tid < 64) {
            const float keep = 1.f - mv;
            float zr_i = zpart[p][gb][0][gu]      + zpart[p][gb][1][gu]
                       + zpart[p][gb][2][gu]      + zpart[p][gb][3][gu];
            float zr_f = zpart[p][gb][0][32 + gu] + zpart[p][gb][1][32 + gu]
                       + zpart[p][gb][2][32 + gu] + zpart[p][gb][3][32 + gu];
            float zr_g = zpart[p][gb][0][64 + gu] + zpart[p][gb][1][64 + gu]
                       + zpart[p][gb][2][64 + gu] + zpart[p][gb][3][64 + gu];
            float zr_o = zpart[p][gb][0][96 + gu] + zpart[p][gb][1][96 + gu]
                       + zpart[p][gb][2][96 + gu] + zpart[p][gb][3][96 + gu];
            float zi = xi + keep * zr_i;
            float zf = xf + keep * zr_f;
            float zg = xg + keep * zr_g;
            float zo = xo + keep * zr_o;

            float ig = 1.f / (1.f + __expf(-zi));
            float fg = 1.f / (1.f + __expf(-zf));
            float gg = 1.f - 2.f / (__expf(2.f * zg) + 1.f);
            float og = 1.f / (1.f + __expf(-zo));

            float c = fg * (keep * c_st) + ig * gg;
            c_st = c;
            float th = 1.f - 2.f / (__expf(2.f * c) + 1.f);
            float hh = og * th;

            if (t < TT - 1) {
                const int pn = p ^ 1;
                // stage this warp's 32 h values, reload as 16-B chunks, and
                // push to all peers: lane l sends chunk (l&7) to peers
                // (l>>3) and (l>>3)+4.
                hstage[gb][gu] = hh;
                __syncwarp();
                {
                    const int chunk = gu & 7;
                    const uint32_t p1 = (uint32_t)(gu >> 3);
                    uint4 v = *(const uint4*)&hstage[gb][chunk * 4];
                    uint32_t laddr = hbase +
                        (uint32_t)(((pn * 2 + gb) * HH + rank * 32 + chunk * 4) * 4);
                    uint32_t lmb = mbase + (uint32_t)(pn * 8);
                    stasync_v4(laddr, lmb, p1,      v);
                    stasync_v4(laddr, lmb, p1 + 4u, v);
                }

                out[(size_t)(rowoff + (unsigned)t) * HH + rank * 32 + gu] = hh;

                // prefetch next step's x/M (latency hides under peers' work)
                const float* xr = g_xz + (size_t)(rowoff + (unsigned)t + 1u) * G4
                                  + rank * 32 + gu;
                xi = xr[0]; xf = xr[HH]; xg = xr[2 * HH]; xo = xr[3 * HH];
                mv = M[rowoff + (unsigned)t + 1u];
            } else {
                out[(size_t)(rowoff + (unsigned)t) * HH + rank * 32 + gu] = hh;
            }
        }
    }
    cl_sync();   // don't exit while peers may still write our smem
}

// ---------------- launch ---------------------------------------------------
extern "C" void kernel_launch(void* const* d_in, const int* in_sizes, int n_in,
                              void* d_out, int out_size) {
    const float* obs     = (const float*)d_in[0];
    const float* S       = (const float*)d_in[1];
    const float* M       = (const float*)d_in[2];
    const float* W_embed = (const float*)d_in[3];
    const float* b_embed = (const float*)d_in[4];
    const float* kern    = (const float*)d_in[5];
    const float* rec     = (const float*)d_in[6];
    const float* bias    = (const float*)d_in[7];
    float* out = (float*)d_out;

    prep_kernel<<<65, 1024>>>(W_embed, b_embed, kern, bias);
    xz_kernel<<<4096, 256>>>(obs);
    rec_kernel<<<128, 512>>>(S, M, rec, out);
}

// round 8
// speedup vs baseline: 1.5881x; 1.3213x over previous
#include <cuda_runtime.h>
#include <cstdint>
#include <cstddef>

// Problem constants
#define BB   32
#define TT   2048
#define HH   256
#define OBS  64
#define EMB  128
#define G4   1024   // 4*H

// ---------------- device scratch (no allocations allowed) ----------------
__device__ float g_xz[(size_t)BB * TT * G4];   // 256 MB: x-path preactivations
__device__ float g_Wc[OBS * G4];               // W_embed @ kernel
__device__ float g_bc[G4];                     // b_embed @ kernel + bias

// ---------------- kernel 1: fold the two dense layers --------------------
__global__ void prep_kernel(const float* __restrict__ W_embed,
                            const float* __restrict__ b_embed,
                            const float* __restrict__ kern,
                            const float* __restrict__ bias) {
    int j = threadIdx.x;       // 0..1023
    int i = blockIdx.x;        // 0..64 (64 = bc row)
    if (i < OBS) {
        float acc = 0.f;
        #pragma unroll 4
        for (int e = 0; e < EMB; e++)
            acc += W_embed[i * EMB + e] * kern[e * G4 + j];
        g_Wc[i * G4 + j] = acc;
    } else {
        float acc = bias[j];
        #pragma unroll 4
        for (int e = 0; e < EMB; e++)
            acc += b_embed[e] * kern[e * G4 + j];
        g_bc[j] = acc;
    }
}

// ---------------- kernel 2: xz = obs @ Wc + bc ----------------------------
#define K2_ROWS 32
__global__ void __launch_bounds__(256) xz_kernel(const float* __restrict__ obs) {
    __shared__ float obs_s[OBS * K2_ROWS];  // [k][r]
    int bid    = blockIdx.x;
    int colBlk = bid & 1;
    int rowBlk = bid >> 1;
    int row0   = rowBlk * K2_ROWS;
    int col0   = colBlk * 512;
    int tid    = threadIdx.x;

    for (int idx = tid; idx < OBS * K2_ROWS; idx += 256) {
        int r = idx >> 6, k = idx & 63;
        obs_s[k * K2_ROWS + r] = obs[(size_t)(row0 + r) * OBS + k];
    }
    __syncthreads();

    int c0 = col0 + tid;
    int c1 = c0 + 256;
    float acc0[K2_ROWS], acc1[K2_ROWS];
    #pragma unroll
    for (int r = 0; r < K2_ROWS; r++) { acc0[r] = 0.f; acc1[r] = 0.f; }

    #pragma unroll 2
    for (int k = 0; k < OBS; k++) {
        float w0 = g_Wc[k * G4 + c0];
        float w1 = g_Wc[k * G4 + c1];
        #pragma unroll
        for (int r = 0; r < K2_ROWS; r += 4) {
            float4 o4 = *(const float4*)&obs_s[k * K2_ROWS + r];
            acc0[r + 0] += o4.x * w0; acc0[r + 1] += o4.y * w0;
            acc0[r + 2] += o4.z * w0; acc0[r + 3] += o4.w * w0;
            acc1[r + 0] += o4.x * w1; acc1[r + 1] += o4.y * w1;
            acc1[r + 2] += o4.z * w1; acc1[r + 3] += o4.w * w1;
        }
    }
    float b0 = g_bc[c0], b1 = g_bc[c1];
    #pragma unroll
    for (int r = 0; r < K2_ROWS; r++) {
        size_t row = (size_t)(row0 + r);
        g_xz[row * G4 + c0] = acc0[r] + b0;
        g_xz[row * G4 + c1] = acc1[r] + b1;
    }
}

// ---------------- kernel 3: masked LSTM recurrence ------------------------
// 8 clusters x 8 CTAs; cluster owns batches {4c..4c+3}; CTA rank owns 32
// hidden units (128 gate cols). 512 threads = (col 0..127, kq 0..3); each
// thread holds its 64-k R slice as 32 packed f32x2 regs and advances FOUR
// batches per step (amortizes the fixed per-step latency chain). h exchange:
// 16-B st.async.v4. Only warp 0 polls the mbarrier; __syncthreads releases
// the CTA. TX accounting (R7 bug fixed): each destination receives
// NB*32 units/source? no -- 32 units * NB batches * 4 B from EACH of CLU
// sources = NB*32*4*CLU bytes total.
#define CLU 8
#define NB  4                           // batches per cluster
#define TX_BYTES (NB * 32 * CLU * 4)    // 4096 B received per CTA per step

__device__ __forceinline__ void ffma2(unsigned long long& d,
                                      unsigned long long a,
                                      unsigned long long b) {
    asm("fma.rn.f32x2 %0, %1, %2, %0;" : "+l"(d) : "l"(a), "l"(b));
}
__device__ __forceinline__ unsigned long long packf2(float lo, float hi) {
    unsigned long long r;
    asm("mov.b64 %0, {%1,%2};" : "=l"(r) : "f"(lo), "f"(hi));
    return r;
}
__device__ __forceinline__ float pairsum(unsigned long long a) {
    float lo, hi;
    asm("mov.b64 {%0,%1}, %2;" : "=f"(lo), "=f"(hi) : "l"(a));
    return lo + hi;
}
// 16-B remote store with tx-signal on the peer's mbarrier
__device__ __forceinline__ void stasync_v4(uint32_t laddr, uint32_t lmbar,
                                           uint32_t peer, uint4 v) {
    asm volatile(
        "{\n\t.reg .b32 ra, rb;\n\t"
        "mapa.shared::cluster.u32 ra, %0, %1;\n\t"
        "mapa.shared::cluster.u32 rb, %2, %1;\n\t"
        "st.async.shared::cluster.mbarrier::complete_tx::bytes.v4.b32"
        " [ra], {%3,%4,%5,%6}, [rb];\n\t}"
        :: "r"(laddr), "r"(peer), "r"(lmbar),
           "r"(v.x), "r"(v.y), "r"(v.z), "r"(v.w) : "memory");
}
__device__ __forceinline__ void mbar_init(uint32_t mbar, uint32_t cnt) {
    asm volatile("mbarrier.init.shared.b64 [%0], %1;" :: "r"(mbar), "r"(cnt) : "memory");
}
__device__ __forceinline__ void mbar_arm(uint32_t mbar, uint32_t tx) {
    asm volatile("mbarrier.arrive.expect_tx.shared.b64 _, [%0], %1;"
                 :: "r"(mbar), "r"(tx) : "memory");
}
__device__ __forceinline__ void mbar_wait(uint32_t mbar, uint32_t parity) {
    uint32_t done;
    asm volatile(
        "{\n\t.reg .pred p;\n\t"
        "mbarrier.try_wait.parity.acquire.cluster.shared::cta.b64 p, [%1], %2;\n\t"
        "selp.b32 %0, 1, 0, p;\n\t}"
        : "=r"(done) : "r"(mbar), "r"(parity) : "memory");
    if (!done) {
        asm volatile(
            "{\n\t.reg .pred P1;\n\t"
            "W_%=:\n\t"
            "mbarrier.try_wait.parity.acquire.cluster.shared::cta.b64 P1, [%0], %1, 0x989680;\n\t"
            "@P1 bra.uni D_%=;\n\t"
            "bra.uni W_%=;\n\t"
            "D_%=:\n\t}"
            :: "r"(mbar), "r"(parity) : "memory");
    }
}
__device__ __forceinline__ void cl_sync() {
    asm volatile("barrier.cluster.arrive.aligned;" ::: "memory");
    asm volatile("barrier.cluster.wait.aligned;" ::: "memory");
}

__global__ void __launch_bounds__(512, 1) __cluster_dims__(CLU, 1, 1)
rec_kernel(const float* __restrict__ S, const float* __restrict__ M,
           const float* __restrict__ rec, float* __restrict__ out) {
    __shared__ __align__(16) float hbuf[2][NB][HH];    // [parity][batch][k]
    __shared__ __align__(16) float hstage[NB][32];     // [batch][unit]
    __shared__ float zpart[2][NB][4][128];             // [parity][batch][kq][col]
    __shared__ __align__(8) unsigned long long mbar[2];

    const int tid  = threadIdx.x;
    const int rank = blockIdx.x & (CLU - 1);
    const int cid  = blockIdx.x / CLU;
    const int b0g  = cid * NB;

    const int col  = tid & 127;
    const int kq   = tid >> 7;            // 0..3
    const int gate = col >> 5;
    const int ul   = col & 31;
    const int j    = gate * HH + rank * 32 + ul;   // global gate column
    const int k0   = kq * 64;

    const uint32_t hbase = (uint32_t)__cvta_generic_to_shared(&hbuf[0][0][0]);
    const uint32_t mbase = (uint32_t)__cvta_generic_to_shared(&mbar[0]);

    // R slice -> registers as adjacent-k f32x2 pairs (32 u64 regs)
    unsigned long long R2[32];
    #pragma unroll
    for (int i = 0; i < 32; i++) {
        float r0 = rec[(unsigned)(k0 + 2 * i)     * G4 + j];
        float r1 = rec[(unsigned)(k0 + 2 * i + 1) * G4 + j];
        R2[i] = packf2(r0, r1);
    }

    // mbarriers: count=1 (the arming arrive); arm both for first uses
    if (tid == 0) {
        mbar_init(mbase, 1);
        mbar_init(mbase + 8, 1);
        asm volatile("fence.mbarrier_init.release.cluster;" ::: "memory");
        mbar_arm(mbase, TX_BYTES);
        mbar_arm(mbase + 8, TX_BYTES);
    }

    // Init h (parity 0) and c from S = [h | c]
    for (int idx = tid; idx < NB * HH; idx += 512) {
        int b = idx >> 8, k = idx & 255;
        hbuf[0][b][k] = S[(unsigned)(b0g + b) * (2 * HH) + k];
    }
    const int gb = tid >> 5, gu = tid & 31;   // epilogue coords (tid<128)
    float c_st = 0.f;
    if (tid < 32 * NB)
        c_st = S[(unsigned)(b0g + gb) * (2 * HH) + HH + rank * 32 + gu];
    __syncthreads();
    cl_sync();   // all peers' mbarriers initialized+armed, hbuf[0] ready

    // Prefetch x-path + mask for t=0
    float xi = 0.f, xf = 0.f, xg = 0.f, xo = 0.f, mv = 0.f;
    unsigned rowoff = 0;
    if (tid < 32 * NB) {
        rowoff = (unsigned)(b0g + gb) * TT;
        const float* xr = g_xz + (size_t)rowoff * G4 + rank * 32 + gu;
        xi = xr[0]; xf = xr[HH]; xg = xr[2 * HH]; xo = xr[3 * HH];
        mv = M[rowoff];
    }

    int ph0 = 0, ph1 = 0;

    for (int t = 0; t < TT; t++) {
        const int p = t & 1;

        if (t > 0) {
            // warp 0 polls for this step's h; arm for the next use; then
            // __syncthreads releases the whole CTA (acquire chains via bar)
            if (tid < 32) {
                if (p) { mbar_wait(mbase + 8, ph1); }
                else   { mbar_wait(mbase,     ph0); }
                if (tid == 0) mbar_arm(mbase + (p ? 8u : 0u), TX_BYTES);
            }
            __syncthreads();
            if (p) ph1 ^= 1; else ph0 ^= 1;
        }

        const ulonglong2* H0 = (const ulonglong2*)&hbuf[p][0][k0];
        const ulonglong2* H1 = (const ulonglong2*)&hbuf[p][1][k0];
        const ulonglong2* H2 = (const ulonglong2*)&hbuf[p][2][k0];
        const ulonglong2* H3 = (const ulonglong2*)&hbuf[p][3][k0];
        unsigned long long a00 = 0, a01 = 0, a10 = 0, a11 = 0;
        unsigned long long a20 = 0, a21 = 0, a30 = 0, a31 = 0;
        #pragma unroll
        for (int i = 0; i < 16; i++) {
            ulonglong2 h0 = H0[i];
            ulonglong2 h1 = H1[i];
            ulonglong2 h2 = H2[i];
            ulonglong2 h3 = H3[i];
            ffma2(a00, R2[2 * i],     h0.x);
            ffma2(a01, R2[2 * i + 1], h0.y);
            ffma2(a10, R2[2 * i],     h1.x);
            ffma2(a11, R2[2 * i + 1], h1.y);
            ffma2(a20, R2[2 * i],     h2.x);
            ffma2(a21, R2[2 * i + 1], h2.y);
            ffma2(a30, R2[2 * i],     h3.x);
            ffma2(a31, R2[2 * i + 1], h3.y);
        }
        zpart[p][0][kq][col] = pairsum(a00) + pairsum(a01);
        zpart[p][1][kq][col] = pairsum(a10) + pairsum(a11);
        zpart[p][2][kq][col] = pairsum(a20) + pairsum(a21);
        zpart[p][3][kq][col] = pairsum(a30) + pairsum(a31);
        __syncthreads();

        if (tid < 32 * NB) {
            const float keep = 1.f - mv;
            float zr_i = zpart[p][gb][0][gu]      + zpart[p][gb][1][gu]
                       + zpart[p][gb][2][gu]      + zpart[p][gb][3][gu];
            float zr_f = zpart[p][gb][0][32 + gu] + zpart[p][gb][1][32 + gu]
                       + zpart[p][gb][2][32 + gu] + zpart[p][gb][3][32 + gu];
            float zr_g = zpart[p][gb][0][64 + gu] + zpart[p][gb][1][64 + gu]
                       + zpart[p][gb][2][64 + gu] + zpart[p][gb][3][64 + gu];
            float zr_o = zpart[p][gb][0][96 + gu] + zpart[p][gb][1][96 + gu]
                       + zpart[p][gb][2][96 + gu] + zpart[p][gb][3][96 + gu];
            float zi = xi + keep * zr_i;
            float zf = xf + keep * zr_f;
            float zg = xg + keep * zr_g;
            float zo = xo + keep * zr_o;

            float ig = 1.f / (1.f + __expf(-zi));
            float fg = 1.f / (1.f + __expf(-zf));
            float gg = 1.f - 2.f / (__expf(2.f * zg) + 1.f);
            float og = 1.f / (1.f + __expf(-zo));

            float c = fg * (keep * c_st) + ig * gg;
            c_st = c;
            float th = 1.f - 2.f / (__expf(2.f * c) + 1.f);
            float hh = og * th;

            if (t < TT - 1) {
                const int pn = p ^ 1;
                // stage this warp's 32 h values, reload as 16-B chunks, and
                // push to all peers: lane l sends chunk (l&7) to peers
                // (l>>3) and (l>>3)+4.
                hstage[gb][gu] = hh;
                __syncwarp();
                {
                    const int chunk = gu & 7;
                    const uint32_t p1 = (uint32_t)(gu >> 3);
                    uint4 v = *(const uint4*)&hstage[gb][chunk * 4];
                    uint32_t laddr = hbase +
                        (uint32_t)(((pn * NB + gb) * HH + rank * 32 + chunk * 4) * 4);
                    uint32_t lmb = mbase + (uint32_t)(pn * 8);
                    stasync_v4(laddr, lmb, p1,      v);
                    stasync_v4(laddr, lmb, p1 + 4u, v);
                }

                out[(size_t)(rowoff + (unsigned)t) * HH + rank * 32 + gu] = hh;

                // prefetch next step's x/M (latency hides under peers' work)
                const float* xr = g_xz + (size_t)(rowoff + (unsigned)t + 1u) * G4
                                  + rank * 32 + gu;
                xi = xr[0]; xf = xr[HH]; xg = xr[2 * HH]; xo = xr[3 * HH];
                mv = M[rowoff + (unsigned)t + 1u];
            } else {
                out[(size_t)(rowoff + (unsigned)t) * HH + rank * 32 + gu] = hh;
            }
        }
    }
    cl_sync();   // don't exit while peers may still write our smem
}

// ---------------- launch ---------------------------------------------------
extern "C" void kernel_launch(void* const* d_in, const int* in_sizes, int n_in,
                              void* d_out, int out_size) {
    const float* obs     = (const float*)d_in[0];
    const float* S       = (const float*)d_in[1];
    const float* M       = (const float*)d_in[2];
    const float* W_embed = (const float*)d_in[3];
    const float* b_embed = (const float*)d_in[4];
    const float* kern    = (const float*)d_in[5];
    const float* rec     = (const float*)d_in[6];
    const float* bias    = (const float*)d_in[7];
    float* out = (float*)d_out;

    prep_kernel<<<65, 1024>>>(W_embed, b_embed, kern, bias);
    xz_kernel<<<4096, 256>>>(obs);
    rec_kernel<<<BB / NB * CLU, 512>>>(S, M, rec, out);
}